// round 1
// baseline (speedup 1.0000x reference)
#include <cuda_runtime.h>
#include <math_constants.h>
#include <cstddef>

// Problem constants
#define Bb 2
#define Qq 2048
#define Kk 2048
#define DMm 512
#define Hh 8
#define Ff 5
#define DHh 64
#define TK 64

// Scratch (alloc-free rule: __device__ globals)
__device__ float g_q[Bb * Qq * DMm];
__device__ float g_k[Bb * Kk * DMm];
__device__ float g_v[Bb * Kk * DMm];
__device__ float g_ctx[Bb * Qq * DMm];

// ---------------------------------------------------------------------------
// GEMM: C[M,512] = (A[M,512] @ W[512,512] + bias[512]) * scale
// 64x64 C-tile, 256 threads, 4x4 micro-tile, k-step 16.
// ---------------------------------------------------------------------------
__global__ __launch_bounds__(256) void gemm512_kernel(
    const float* __restrict__ A, const float* __restrict__ W,
    const float* __restrict__ bias, float* __restrict__ C, float scale)
{
    __shared__ __align__(16) float As[64][16];
    __shared__ __align__(16) float Ws[16][64];

    const int tid = threadIdx.x;
    const int tx = tid & 15;
    const int ty = tid >> 4;
    const int rowBase = blockIdx.y * 64;
    const int colBase = blockIdx.x * 64;

    float acc[4][4];
#pragma unroll
    for (int i = 0; i < 4; ++i)
#pragma unroll
        for (int j = 0; j < 4; ++j) acc[i][j] = 0.f;

    for (int k0 = 0; k0 < 512; k0 += 16) {
#pragma unroll
        for (int i = 0; i < 4; ++i) {
            int idx = tid + i * 256;
            int r = idx >> 4, c = idx & 15;
            As[r][c] = A[(size_t)(rowBase + r) * 512 + (k0 + c)];
            int r2 = idx >> 6, c2 = idx & 63;
            Ws[r2][c2] = W[(size_t)(k0 + r2) * 512 + (colBase + c2)];
        }
        __syncthreads();
#pragma unroll
        for (int kk = 0; kk < 16; ++kk) {
            float a4[4];
#pragma unroll
            for (int i = 0; i < 4; ++i) a4[i] = As[ty * 4 + i][kk];
            float4 w4 = *reinterpret_cast<const float4*>(&Ws[kk][tx * 4]);
            float wv[4] = {w4.x, w4.y, w4.z, w4.w};
#pragma unroll
            for (int i = 0; i < 4; ++i)
#pragma unroll
                for (int j = 0; j < 4; ++j)
                    acc[i][j] = fmaf(a4[i], wv[j], acc[i][j]);
        }
        __syncthreads();
    }

#pragma unroll
    for (int i = 0; i < 4; ++i) {
#pragma unroll
        for (int j = 0; j < 4; ++j) {
            int rr = rowBase + ty * 4 + i;
            int cc = colBase + tx * 4 + j;
            C[(size_t)rr * 512 + cc] = (acc[i][j] + bias[cc]) * scale;
        }
    }
}

// ---------------------------------------------------------------------------
// Fused attention: scores = q.k + TISA bias, online softmax (valid_lens mask
// handled by clamping the key loop), P@V.  One thread per query row.
// Grid: (Q/128, H, B), 128 threads.
// ---------------------------------------------------------------------------
__global__ __launch_bounds__(128) void attn_kernel(
    const float* __restrict__ qlocs, const float* __restrict__ klocs,
    const float* __restrict__ apar, const float* __restrict__ bpar,
    const float* __restrict__ cpar, const int* __restrict__ valid_lens)
{
    __shared__ __align__(16) float Ks[TK][DHh];
    __shared__ __align__(16) float Vs[TK][DHh];
    __shared__ float Ls[TK][2];

    const int tid = threadIdx.x;
    const int h = blockIdx.y;
    const int b = blockIdx.z;
    const int qrow = blockIdx.x * 128 + tid;

    // Per-head RBF params
    float af[Ff], bf[Ff], cf[Ff];
#pragma unroll
    for (int f = 0; f < Ff; ++f) {
        af[f] = apar[h * Ff + f];
        bf[f] = fabsf(bpar[h * Ff + f]);
        cf[f] = cpar[h * Ff + f];
    }

    const float qx = qlocs[(size_t)(b * Qq + qrow) * 2 + 0];
    const float qy = qlocs[(size_t)(b * Qq + qrow) * 2 + 1];

    // Query vector (already scaled by 1/sqrt(DH) in the projection GEMM)
    float qv[DHh];
    const float* qptr = g_q + (size_t)(b * Qq + qrow) * DMm + h * DHh;
#pragma unroll
    for (int d = 0; d < DHh; d += 4) {
        float4 t = *reinterpret_cast<const float4*>(qptr + d);
        qv[d] = t.x; qv[d + 1] = t.y; qv[d + 2] = t.z; qv[d + 3] = t.w;
    }

    float acc[DHh];
#pragma unroll
    for (int d = 0; d < DHh; ++d) acc[d] = 0.f;
    float m = -CUDART_INF_F;
    float l = 0.f;

    const int kend = valid_lens[b];

    for (int kt0 = 0; kt0 < kend; kt0 += TK) {
        __syncthreads();
        // Cooperative load: TK*DH = 4096 floats per array = 1024 float4;
        // 128 threads -> 8 float4 each.
#pragma unroll
        for (int i = 0; i < 8; ++i) {
            int v = tid + i * 128;           // 0..1023
            int r = v >> 4;
            int c = (v & 15) << 2;
            size_t base = (size_t)(b * Kk + kt0 + r) * DMm + h * DHh + c;
            *reinterpret_cast<float4*>(&Ks[r][c]) =
                *reinterpret_cast<const float4*>(g_k + base);
            *reinterpret_cast<float4*>(&Vs[r][c]) =
                *reinterpret_cast<const float4*>(g_v + base);
        }
        if (tid < TK * 2) {
            int r = tid >> 1, c2 = tid & 1;
            Ls[r][c2] = klocs[(size_t)(b * Kk + kt0 + r) * 2 + c2];
        }
        __syncthreads();

        const int jmax = min(TK, kend - kt0);
        for (int j = 0; j < jmax; ++j) {
            // q . k  (shared broadcast: all threads read the same address)
            float s = 0.f;
#pragma unroll
            for (int d = 0; d < DHh; ++d) s = fmaf(qv[d], Ks[j][d], s);

            // TISA RBF bias
            float dx = qx - Ls[j][0];
            float dy = qy - Ls[j][1];
            float dist = sqrtf(fmaf(dx, dx, dy * dy));
#pragma unroll
            for (int f = 0; f < Ff; ++f) {
                float t = dist - cf[f];
                s = fmaf(af[f], __expf(-bf[f] * t * t), s);
            }

            // Online softmax: rescale only when max changes (rare)
            if (s > m) {
                float corr = __expf(m - s);   // __expf(-inf)=0 handles first key
                l *= corr;
#pragma unroll
                for (int d = 0; d < DHh; ++d) acc[d] *= corr;
                m = s;
            }
            float p = __expf(s - m);
            l += p;
#pragma unroll
            for (int d = 0; d < DHh; ++d) acc[d] = fmaf(p, Vs[j][d], acc[d]);
        }
    }

    const float invl = 1.f / l;
    float* optr = g_ctx + (size_t)(b * Qq + qrow) * DMm + h * DHh;
#pragma unroll
    for (int d = 0; d < DHh; d += 4) {
        float4 t;
        t.x = acc[d] * invl;
        t.y = acc[d + 1] * invl;
        t.z = acc[d + 2] * invl;
        t.w = acc[d + 3] * invl;
        *reinterpret_cast<float4*>(optr + d) = t;
    }
}

// ---------------------------------------------------------------------------
// Launch
// Input order (metadata): 0 qs, 1 ks, 2 vs, 3 qs_locs, 4 ks_locs,
// 5 Wq, 6 bq, 7 Wk, 8 bk, 9 Wv, 10 bv, 11 Wo, 12 bo, 13 a, 14 b, 15 c,
// 16 valid_lens
// ---------------------------------------------------------------------------
extern "C" void kernel_launch(void* const* d_in, const int* in_sizes, int n_in,
                              void* d_out, int out_size)
{
    const float* qs      = (const float*)d_in[0];
    const float* ks      = (const float*)d_in[1];
    const float* vs      = (const float*)d_in[2];
    const float* qs_locs = (const float*)d_in[3];
    const float* ks_locs = (const float*)d_in[4];
    const float* Wq      = (const float*)d_in[5];
    const float* bq      = (const float*)d_in[6];
    const float* Wk      = (const float*)d_in[7];
    const float* bk      = (const float*)d_in[8];
    const float* Wv      = (const float*)d_in[9];
    const float* bv      = (const float*)d_in[10];
    const float* Wo      = (const float*)d_in[11];
    const float* bo      = (const float*)d_in[12];
    const float* ap      = (const float*)d_in[13];
    const float* bp      = (const float*)d_in[14];
    const float* cp      = (const float*)d_in[15];
    const int*   vlen    = (const int*)d_in[16];
    float* out           = (float*)d_out;

    float *pq, *pk, *pv, *pctx;
    cudaGetSymbolAddress((void**)&pq,   g_q);
    cudaGetSymbolAddress((void**)&pk,   g_k);
    cudaGetSymbolAddress((void**)&pv,   g_v);
    cudaGetSymbolAddress((void**)&pctx, g_ctx);

    const float qscale = 1.0f / 8.0f;  // 1/sqrt(DH=64)
    dim3 ggrid(512 / 64, (Bb * Qq) / 64);  // (8, 64)

    gemm512_kernel<<<ggrid, 256>>>(qs, Wq, bq, pq, qscale);
    gemm512_kernel<<<ggrid, 256>>>(ks, Wk, bk, pk, 1.0f);
    gemm512_kernel<<<ggrid, 256>>>(vs, Wv, bv, pv, 1.0f);

    dim3 agrid(Qq / 128, Hh, Bb);  // (16, 8, 2)
    attn_kernel<<<agrid, 128>>>(qs_locs, ks_locs, ap, bp, cp, vlen);

    gemm512_kernel<<<ggrid, 256>>>(pctx, Wo, bo, out, 1.0f);
}